// round 2
// baseline (speedup 1.0000x reference)
#include <cuda_runtime.h>
#include <math.h>

#define NUM_CLASSES 1000
#define FEAT_DIM    256
#define NROWS       262144
#define ALPHA       0.5f

// ---- scratch (device globals; no allocation allowed) ----------------------
__device__ float g_sums[NUM_CLASSES * FEAT_DIM];   // per-class feature sums
__device__ float g_counts[NUM_CLASSES];            // per-class counts (float)
__device__ int   g_hist[NUM_CLASSES];              // label histogram
__device__ int   g_cursor[NUM_CLASSES];            // scatter cursors
__device__ int   g_sorted[NROWS];                  // (label<<18) | row
__device__ float g_loss;
__device__ int   g_is64;

// ---------------------------------------------------------------------------
// K0: zero all scratch + detect label dtype. 256K f32 = 64K float4.
// ---------------------------------------------------------------------------
__global__ void cl_zero_kernel(const void* __restrict__ labels_raw) {
    int i = blockIdx.x * blockDim.x + threadIdx.x;
    // g_sums: 65536 float4
    if (i < (NUM_CLASSES * FEAT_DIM) / 4)
        ((float4*)g_sums)[i] = make_float4(0.f, 0.f, 0.f, 0.f);
    if (i < NUM_CLASSES) {
        g_counts[i] = 0.0f;
        g_hist[i] = 0;
    }
    if (i == 0) {
        g_loss = 0.0f;
        // int64 labels < 1000 -> every odd 32-bit word is zero.
        const int* w = (const int*)labels_raw;
        int all_zero = 1;
        #pragma unroll 8
        for (int k = 0; k < 64; k++)
            if (w[2 * k + 1] != 0) { all_zero = 0; break; }
        g_is64 = all_zero;
    }
}

__device__ __forceinline__ int load_label(const void* labels_raw, int i, int is64) {
    return is64 ? (int)((const long long*)labels_raw)[i]
                : ((const int*)labels_raw)[i];
}

// ---------------------------------------------------------------------------
// K1: histogram of labels (smem-privatized)
// ---------------------------------------------------------------------------
__global__ void __launch_bounds__(256)
cl_hist_kernel(const void* __restrict__ labels_raw) {
    __shared__ int sh[NUM_CLASSES];
    for (int j = threadIdx.x; j < NUM_CLASSES; j += blockDim.x) sh[j] = 0;
    __syncthreads();
    const int is64 = g_is64;
    int stride = gridDim.x * blockDim.x;
    for (int i = blockIdx.x * blockDim.x + threadIdx.x; i < NROWS; i += stride)
        atomicAdd(&sh[load_label(labels_raw, i, is64)], 1);
    __syncthreads();
    for (int j = threadIdx.x; j < NUM_CLASSES; j += blockDim.x)
        if (sh[j]) atomicAdd(&g_hist[j], sh[j]);
}

// ---------------------------------------------------------------------------
// K2: exclusive scan of 1000 bins (single block, Hillis-Steele)
// ---------------------------------------------------------------------------
__global__ void cl_scan_kernel() {
    __shared__ int sh[1024];
    int t = threadIdx.x;
    int v = (t < NUM_CLASSES) ? g_hist[t] : 0;
    sh[t] = v;
    __syncthreads();
    #pragma unroll
    for (int off = 1; off < 1024; off <<= 1) {
        int add = (t >= off) ? sh[t - off] : 0;
        __syncthreads();
        sh[t] += add;
        __syncthreads();
    }
    if (t < NUM_CLASSES) {
        int excl = sh[t] - v;
        g_cursor[t] = excl;
        g_counts[t] = (float)v;   // counts known exactly here; skip atomics later
    }
}

// ---------------------------------------------------------------------------
// K3: scatter row indices into sorted order; pack (label<<18 | row)
// ---------------------------------------------------------------------------
__global__ void __launch_bounds__(256)
cl_scatter_kernel(const void* __restrict__ labels_raw) {
    const int is64 = g_is64;
    int stride = gridDim.x * blockDim.x;
    for (int i = blockIdx.x * blockDim.x + threadIdx.x; i < NROWS; i += stride) {
        int lbl = load_label(labels_raw, i, is64);
        int pos = atomicAdd(&g_cursor[lbl], 1);
        g_sorted[pos] = (lbl << 18) | i;
    }
}

// Vectorized reduction-add to global (sm_90+)
__device__ __forceinline__ void red_add_v4(float* addr, float4 v) {
    asm volatile("red.global.add.v4.f32 [%0], {%1, %2, %3, %4};"
                 :: "l"(addr), "f"(v.x), "f"(v.y), "f"(v.z), "f"(v.w)
                 : "memory");
}

__device__ __forceinline__ float4 f4add(float4 a, float4 b) {
    return make_float4(a.x + b.x, a.y + b.y, a.z + b.z, a.w + b.w);
}

// ---------------------------------------------------------------------------
// K4: main fused pass over sorted rows. One warp = one contiguous chunk.
// Lane l covers dims [4l,4l+4) and [128+4l, 128+4l+4).
// Center held in registers per segment; sums accumulated in registers,
// flushed with red.v4 only at segment boundaries.
// ---------------------------------------------------------------------------
#define MAIN_BLOCKS 592
#define MAIN_THREADS 256
#define TOTAL_WARPS (MAIN_BLOCKS * (MAIN_THREADS / 32))

__global__ void __launch_bounds__(MAIN_THREADS)
cl_main_kernel(const float* __restrict__ x,
               const float* __restrict__ centers) {
    __shared__ float s_loss;
    if (threadIdx.x == 0) s_loss = 0.0f;
    __syncthreads();

    const int lane  = threadIdx.x & 31;
    const int gwarp = blockIdx.x * (MAIN_THREADS / 32) + (threadIdx.x >> 5);
    const int chunk = (NROWS + TOTAL_WARPS - 1) / TOTAL_WARPS;
    int pos = gwarp * chunk;
    int end = pos + chunk;
    if (end > NROWS) end = NROWS;

    float loss_acc = 0.0f;           // lane 0 only
    float4 acc_a = make_float4(0.f, 0.f, 0.f, 0.f);
    float4 acc_b = make_float4(0.f, 0.f, 0.f, 0.f);
    float4 ca = acc_a, cb = acc_b;
    int cur_lbl = -1;

    for (; pos < end; pos++) {
        int e = g_sorted[pos];
        int lbl = e >> 18;
        int row = e & 0x3FFFF;

        if (lbl != cur_lbl) {
            if (cur_lbl >= 0) {
                float* base = g_sums + (size_t)cur_lbl * FEAT_DIM;
                red_add_v4(base + lane * 4, acc_a);
                red_add_v4(base + 128 + lane * 4, acc_b);
                acc_a = make_float4(0.f, 0.f, 0.f, 0.f);
                acc_b = make_float4(0.f, 0.f, 0.f, 0.f);
            }
            const float4* __restrict__ cr =
                (const float4*)(centers + (size_t)lbl * FEAT_DIM);
            ca = cr[lane];
            cb = cr[lane + 32];
            cur_lbl = lbl;
        }

        const float4* __restrict__ xr =
            (const float4*)(x + (size_t)row * FEAT_DIM);
        float4 xa = xr[lane];
        float4 xb = xr[lane + 32];

        acc_a = f4add(acc_a, xa);
        acc_b = f4add(acc_b, xb);

        float d0 = xa.x - ca.x, d1 = xa.y - ca.y, d2 = xa.z - ca.z, d3 = xa.w - ca.w;
        float e0 = xb.x - cb.x, e1 = xb.y - cb.y, e2 = xb.z - cb.z, e3 = xb.w - cb.w;
        float ss = d0*d0 + d1*d1 + d2*d2 + d3*d3
                 + e0*e0 + e1*e1 + e2*e2 + e3*e3;

        #pragma unroll
        for (int o = 16; o > 0; o >>= 1)
            ss += __shfl_xor_sync(0xFFFFFFFFu, ss, o);
        if (lane == 0) loss_acc += sqrtf(ss);
    }

    if (cur_lbl >= 0) {
        float* base = g_sums + (size_t)cur_lbl * FEAT_DIM;
        red_add_v4(base + lane * 4, acc_a);
        red_add_v4(base + 128 + lane * 4, acc_b);
    }

    if (lane == 0) atomicAdd(&s_loss, loss_acc);
    __syncthreads();
    if (threadIdx.x == 0) atomicAdd(&g_loss, s_loss);
}

// ---------------------------------------------------------------------------
// K5: finalize. out[0] = loss, out[1..256000] = new_centers.
// ---------------------------------------------------------------------------
__global__ void cl_finalize_kernel(const float* __restrict__ centers,
                                   float* __restrict__ out) {
    int i = blockIdx.x * blockDim.x + threadIdx.x;
    if (i == 0) out[0] = g_loss * (0.5f / (float)NROWS);
    if (i < NUM_CLASSES * FEAT_DIM) {
        int c = i / FEAT_DIM;
        float cnt = g_counts[c];
        float cen = centers[i];
        float res = cen;
        if (cnt > 0.0f) {
            float mean = g_sums[i] / cnt;
            res = cen + ALPHA * (mean - cen);
        }
        out[1 + i] = res;
    }
}

// ---------------------------------------------------------------------------
extern "C" void kernel_launch(void* const* d_in, const int* in_sizes, int n_in,
                              void* d_out, int out_size) {
    const float* x       = (const float*)d_in[0];
    const void*  labels  = d_in[1];
    const float* centers = (const float*)d_in[2];
    float*       out     = (float*)d_out;
    (void)in_sizes; (void)n_in; (void)out_size;

    cl_zero_kernel<<<(NUM_CLASSES * FEAT_DIM / 4 + 255) / 256, 256>>>(labels);
    cl_hist_kernel<<<512, 256>>>(labels);
    cl_scan_kernel<<<1, 1024>>>();
    cl_scatter_kernel<<<512, 256>>>(labels);
    cl_main_kernel<<<MAIN_BLOCKS, MAIN_THREADS>>>(x, centers);
    cl_finalize_kernel<<<(NUM_CLASSES * FEAT_DIM + 255) / 256, 256>>>(centers, out);
}

// round 3
// speedup vs baseline: 1.6562x; 1.6562x over previous
#include <cuda_runtime.h>
#include <math.h>

#define NUM_CLASSES 1000
#define FEAT_DIM    256
#define NROWS       262144
#define ALPHA       0.5f

#define NBLK 256          // hist/scatter blocks
#define RPB  1024         // rows per hist/scatter block (NBLK*RPB == NROWS)

// ---- scratch (device globals; no allocation allowed) ----------------------
__device__ float g_sums[NUM_CLASSES * FEAT_DIM];
__device__ float g_counts[NUM_CLASSES];
__device__ int   g_bh[NBLK * NUM_CLASSES];    // per-block histogram [b][c]
__device__ int   g_cur[NBLK * NUM_CLASSES];   // within-class exclusive offsets [b][c]
__device__ int   g_tot[NUM_CLASSES];          // class totals
__device__ int   g_base[NUM_CLASSES];         // class exclusive base
__device__ int   g_sorted[NROWS];             // (label<<18) | row
__device__ float g_loss;
__device__ int   g_is64;

__device__ __forceinline__ int load_label(const void* labels_raw, int i, int is64) {
    return is64 ? (int)((const long long*)labels_raw)[i]
                : ((const int*)labels_raw)[i];
}

// ---------------------------------------------------------------------------
// K1: per-block histogram. Each block handles RPB rows. is64 detected locally.
// ---------------------------------------------------------------------------
__global__ void __launch_bounds__(256)
cl_hist_kernel(const void* __restrict__ labels_raw) {
    __shared__ int sh[NUM_CLASSES];
    for (int j = threadIdx.x; j < NUM_CLASSES; j += 256) sh[j] = 0;
    __syncthreads();

    // local dtype detect (cheap, no cross-kernel dependency)
    const int* w = (const int*)labels_raw;
    int is64 = 1;
    #pragma unroll 8
    for (int k = 0; k < 64; k++)
        if (w[2 * k + 1] != 0) { is64 = 0; break; }

    int base = blockIdx.x * RPB;
    #pragma unroll
    for (int r = 0; r < RPB / 256; r++) {
        int i = base + r * 256 + threadIdx.x;
        atomicAdd(&sh[load_label(labels_raw, i, is64)], 1);
    }
    __syncthreads();
    for (int j = threadIdx.x; j < NUM_CLASSES; j += 256)
        g_bh[blockIdx.x * NUM_CLASSES + j] = sh[j];

    if (blockIdx.x == 0 && threadIdx.x == 0) g_is64 = is64;
}

// ---------------------------------------------------------------------------
// K2: per-class scan over blocks. Block c: exclusive scan of g_bh[*][c],
// writes g_cur[*][c] and g_tot[c]. Also zeroes g_sums row for class c.
// ---------------------------------------------------------------------------
__global__ void __launch_bounds__(256)
cl_cursor_kernel() {
    __shared__ int sh[NBLK];
    int c = blockIdx.x;
    int t = threadIdx.x;
    int v = g_bh[t * NUM_CLASSES + c];
    sh[t] = v;
    __syncthreads();
    #pragma unroll
    for (int off = 1; off < NBLK; off <<= 1) {
        int add = (t >= off) ? sh[t - off] : 0;
        __syncthreads();
        sh[t] += add;
        __syncthreads();
    }
    g_cur[t * NUM_CLASSES + c] = sh[t] - v;      // exclusive
    if (t == NBLK - 1) g_tot[c] = sh[t];
    g_sums[c * FEAT_DIM + t] = 0.0f;             // zero sums (FEAT_DIM==256)
}

// ---------------------------------------------------------------------------
// K3: exclusive scan of class totals -> g_base, g_counts; zero loss.
// ---------------------------------------------------------------------------
__global__ void cl_scan_kernel() {
    __shared__ int sh[1024];
    int t = threadIdx.x;
    int v = (t < NUM_CLASSES) ? g_tot[t] : 0;
    sh[t] = v;
    __syncthreads();
    #pragma unroll
    for (int off = 1; off < 1024; off <<= 1) {
        int add = (t >= off) ? sh[t - off] : 0;
        __syncthreads();
        sh[t] += add;
        __syncthreads();
    }
    if (t < NUM_CLASSES) {
        g_base[t] = sh[t] - v;
        g_counts[t] = (float)v;
    }
    if (t == 0) g_loss = 0.0f;
}

// ---------------------------------------------------------------------------
// K4: scatter with smem-private cursors (deterministic global positions).
// ---------------------------------------------------------------------------
__global__ void __launch_bounds__(256)
cl_scatter_kernel(const void* __restrict__ labels_raw) {
    __shared__ int scur[NUM_CLASSES];
    for (int c = threadIdx.x; c < NUM_CLASSES; c += 256)
        scur[c] = g_base[c] + g_cur[blockIdx.x * NUM_CLASSES + c];
    __syncthreads();

    const int is64 = g_is64;
    int base = blockIdx.x * RPB;
    #pragma unroll
    for (int r = 0; r < RPB / 256; r++) {
        int i = base + r * 256 + threadIdx.x;
        int lbl = load_label(labels_raw, i, is64);
        int pos = atomicAdd(&scur[lbl], 1);      // smem atomic: low contention
        g_sorted[pos] = (lbl << 18) | i;
    }
}

// Vectorized reduction-add to global (sm_90+)
__device__ __forceinline__ void red_add_v4(float* addr, float4 v) {
    asm volatile("red.global.add.v4.f32 [%0], {%1, %2, %3, %4};"
                 :: "l"(addr), "f"(v.x), "f"(v.y), "f"(v.z), "f"(v.w)
                 : "memory");
}
__device__ __forceinline__ float4 f4add(float4 a, float4 b) {
    return make_float4(a.x + b.x, a.y + b.y, a.z + b.z, a.w + b.w);
}

// ---------------------------------------------------------------------------
// K5: main fused pass over sorted rows; register-aggregated segment sums.
// One warp = contiguous chunk of 28 sorted rows. 2-row unrolled pipeline.
// ---------------------------------------------------------------------------
#define MAIN_BLOCKS 1184
#define MAIN_THREADS 256
#define TOTAL_WARPS (MAIN_BLOCKS * (MAIN_THREADS / 32))

__global__ void __launch_bounds__(MAIN_THREADS)
cl_main_kernel(const float* __restrict__ x,
               const float* __restrict__ centers) {
    __shared__ float s_loss;
    if (threadIdx.x == 0) s_loss = 0.0f;
    __syncthreads();

    const int lane  = threadIdx.x & 31;
    const int gwarp = blockIdx.x * (MAIN_THREADS / 32) + (threadIdx.x >> 5);
    const int chunk = (NROWS + TOTAL_WARPS - 1) / TOTAL_WARPS;   // 28
    int pos = gwarp * chunk;
    int end = pos + chunk;
    if (end > NROWS) end = NROWS;

    float loss_acc = 0.0f;
    float4 acc_a = make_float4(0.f, 0.f, 0.f, 0.f);
    float4 acc_b = make_float4(0.f, 0.f, 0.f, 0.f);
    float4 ca = acc_a, cb = acc_b;
    int cur_lbl = -1;

    // process pairs of rows: 4 LDG.128 in flight, overlapped shuffle chains
    for (; pos + 2 <= end; pos += 2) {
        int e0 = g_sorted[pos];
        int e1 = g_sorted[pos + 1];
        int lbl0 = e0 >> 18, row0 = e0 & 0x3FFFF;
        int lbl1 = e1 >> 18, row1 = e1 & 0x3FFFF;

        const float4* __restrict__ xr0 = (const float4*)(x + (size_t)row0 * FEAT_DIM);
        const float4* __restrict__ xr1 = (const float4*)(x + (size_t)row1 * FEAT_DIM);
        float4 xa0 = xr0[lane], xb0 = xr0[lane + 32];
        float4 xa1 = xr1[lane], xb1 = xr1[lane + 32];

        if (lbl0 != cur_lbl) {
            if (cur_lbl >= 0) {
                float* b = g_sums + (size_t)cur_lbl * FEAT_DIM;
                red_add_v4(b + lane * 4, acc_a);
                red_add_v4(b + 128 + lane * 4, acc_b);
                acc_a = make_float4(0.f, 0.f, 0.f, 0.f);
                acc_b = make_float4(0.f, 0.f, 0.f, 0.f);
            }
            const float4* cr = (const float4*)(centers + (size_t)lbl0 * FEAT_DIM);
            ca = cr[lane]; cb = cr[lane + 32];
            cur_lbl = lbl0;
        }
        acc_a = f4add(acc_a, xa0);
        acc_b = f4add(acc_b, xb0);
        float d0 = xa0.x-ca.x, d1 = xa0.y-ca.y, d2 = xa0.z-ca.z, d3 = xa0.w-ca.w;
        float f0 = xb0.x-cb.x, f1 = xb0.y-cb.y, f2 = xb0.z-cb.z, f3 = xb0.w-cb.w;
        float ss0 = d0*d0+d1*d1+d2*d2+d3*d3 + f0*f0+f1*f1+f2*f2+f3*f3;

        if (lbl1 != cur_lbl) {
            float* b = g_sums + (size_t)cur_lbl * FEAT_DIM;
            red_add_v4(b + lane * 4, acc_a);
            red_add_v4(b + 128 + lane * 4, acc_b);
            acc_a = make_float4(0.f, 0.f, 0.f, 0.f);
            acc_b = make_float4(0.f, 0.f, 0.f, 0.f);
            const float4* cr = (const float4*)(centers + (size_t)lbl1 * FEAT_DIM);
            ca = cr[lane]; cb = cr[lane + 32];
            cur_lbl = lbl1;
        }
        acc_a = f4add(acc_a, xa1);
        acc_b = f4add(acc_b, xb1);
        float g0 = xa1.x-ca.x, g1 = xa1.y-ca.y, g2 = xa1.z-ca.z, g3 = xa1.w-ca.w;
        float h0 = xb1.x-cb.x, h1 = xb1.y-cb.y, h2 = xb1.z-cb.z, h3 = xb1.w-cb.w;
        float ss1 = g0*g0+g1*g1+g2*g2+g3*g3 + h0*h0+h1*h1+h2*h2+h3*h3;

        #pragma unroll
        for (int o = 16; o > 0; o >>= 1) {
            ss0 += __shfl_xor_sync(0xFFFFFFFFu, ss0, o);
            ss1 += __shfl_xor_sync(0xFFFFFFFFu, ss1, o);
        }
        if (lane == 0) loss_acc += sqrtf(ss0) + sqrtf(ss1);
    }

    // tail (<=1 row)
    for (; pos < end; pos++) {
        int e = g_sorted[pos];
        int lbl = e >> 18, row = e & 0x3FFFF;
        const float4* __restrict__ xr = (const float4*)(x + (size_t)row * FEAT_DIM);
        float4 xa = xr[lane], xb = xr[lane + 32];
        if (lbl != cur_lbl) {
            if (cur_lbl >= 0) {
                float* b = g_sums + (size_t)cur_lbl * FEAT_DIM;
                red_add_v4(b + lane * 4, acc_a);
                red_add_v4(b + 128 + lane * 4, acc_b);
                acc_a = make_float4(0.f, 0.f, 0.f, 0.f);
                acc_b = make_float4(0.f, 0.f, 0.f, 0.f);
            }
            const float4* cr = (const float4*)(centers + (size_t)lbl * FEAT_DIM);
            ca = cr[lane]; cb = cr[lane + 32];
            cur_lbl = lbl;
        }
        acc_a = f4add(acc_a, xa);
        acc_b = f4add(acc_b, xb);
        float d0 = xa.x-ca.x, d1 = xa.y-ca.y, d2 = xa.z-ca.z, d3 = xa.w-ca.w;
        float f0 = xb.x-cb.x, f1 = xb.y-cb.y, f2 = xb.z-cb.z, f3 = xb.w-cb.w;
        float ss = d0*d0+d1*d1+d2*d2+d3*d3 + f0*f0+f1*f1+f2*f2+f3*f3;
        #pragma unroll
        for (int o = 16; o > 0; o >>= 1)
            ss += __shfl_xor_sync(0xFFFFFFFFu, ss, o);
        if (lane == 0) loss_acc += sqrtf(ss);
    }

    if (cur_lbl >= 0) {
        float* b = g_sums + (size_t)cur_lbl * FEAT_DIM;
        red_add_v4(b + lane * 4, acc_a);
        red_add_v4(b + 128 + lane * 4, acc_b);
    }

    if (lane == 0) atomicAdd(&s_loss, loss_acc);
    __syncthreads();
    if (threadIdx.x == 0) atomicAdd(&g_loss, s_loss);
}

// ---------------------------------------------------------------------------
// K6: finalize. out[0] = loss, out[1..256000] = new_centers.
// ---------------------------------------------------------------------------
__global__ void cl_finalize_kernel(const float* __restrict__ centers,
                                   float* __restrict__ out) {
    int i = blockIdx.x * blockDim.x + threadIdx.x;
    if (i == 0) out[0] = g_loss * (0.5f / (float)NROWS);
    if (i < NUM_CLASSES * FEAT_DIM) {
        int c = i / FEAT_DIM;
        float cnt = g_counts[c];
        float cen = centers[i];
        float res = cen;
        if (cnt > 0.0f) {
            float mean = g_sums[i] / cnt;
            res = cen + ALPHA * (mean - cen);
        }
        out[1 + i] = res;
    }
}

// ---------------------------------------------------------------------------
extern "C" void kernel_launch(void* const* d_in, const int* in_sizes, int n_in,
                              void* d_out, int out_size) {
    const float* x       = (const float*)d_in[0];
    const void*  labels  = d_in[1];
    const float* centers = (const float*)d_in[2];
    float*       out     = (float*)d_out;
    (void)in_sizes; (void)n_in; (void)out_size;

    cl_hist_kernel   <<<NBLK, 256>>>(labels);
    cl_cursor_kernel <<<NUM_CLASSES, NBLK>>>();
    cl_scan_kernel   <<<1, 1024>>>();
    cl_scatter_kernel<<<NBLK, 256>>>(labels);
    cl_main_kernel   <<<MAIN_BLOCKS, MAIN_THREADS>>>(x, centers);
    cl_finalize_kernel<<<(NUM_CLASSES * FEAT_DIM + 256) / 256, 256>>>(centers, out);
}